// round 16
// baseline (speedup 1.0000x reference)
#include <cuda_runtime.h>
#include <cuda_bf16.h>
#include <cstdint>

// Problem constants: B=4, C=128, W=H=64
#define NB  4
#define NCH 64
#define ND  8
#define NN  4096
#define MT  64      // query tile -> grid 256
#define NT  64      // key tile
#define NTILES (NN / NT)
#define VP  72      // v-tile pad (bf16 units)
#define L2E 1.4426950408889634f

// Scratch (no cudaMalloc allowed)
// p2t/p3t per token: PERMUTED pairs [d0,d4, d1,d5, d2,d6, d3,d7]
__device__ __align__(16) float         g_p2t[NB * NN * ND];   // tf32-rounded
__device__ __align__(16) float         g_p3t[NB * NN * ND];   // tf32-rounded
__device__ __align__(16) __nv_bfloat16 g_v3b[NB * NN * NCH];  // [b][n][c] bf16

__device__ __forceinline__ float to_tf32(float x) {
    unsigned u;
    asm("cvt.rna.tf32.f32 %0, %1;" : "=r"(u) : "f"(x));
    return __uint_as_float(u);
}
__device__ __forceinline__ float ex2f(float x) {
    float r;
    asm("ex2.approx.f32 %0, %1;" : "=f"(r) : "f"(x));
    return r;
}
__device__ __forceinline__ unsigned pk_bf16x2(float lo, float hi) {
    unsigned r;
    asm("cvt.rn.bf16x2.f32 %0, %1, %2;" : "=r"(r) : "f"(hi), "f"(lo));
    return r;
}
__device__ __forceinline__ void mma_tf32(float* c,
                                         unsigned a0, unsigned a1, unsigned a2, unsigned a3,
                                         unsigned b0, unsigned b1)
{
    asm volatile(
        "mma.sync.aligned.m16n8k8.row.col.f32.tf32.tf32.f32 "
        "{%0,%1,%2,%3}, {%4,%5,%6,%7}, {%8,%9}, {%0,%1,%2,%3};"
        : "+f"(c[0]), "+f"(c[1]), "+f"(c[2]), "+f"(c[3])
        : "r"(a0), "r"(a1), "r"(a2), "r"(a3), "r"(b0), "r"(b1));
}
__device__ __forceinline__ void mma_bf16(float* c,
                                         unsigned a0, unsigned a1, unsigned a2, unsigned a3,
                                         unsigned b0, unsigned b1)
{
    asm volatile(
        "mma.sync.aligned.m16n8k16.row.col.f32.bf16.bf16.f32 "
        "{%0,%1,%2,%3}, {%4,%5,%6,%7}, {%8,%9}, {%0,%1,%2,%3};"
        : "+f"(c[0]), "+f"(c[1]), "+f"(c[2]), "+f"(c[3])
        : "r"(a0), "r"(a1), "r"(a2), "r"(a3), "r"(b0), "r"(b1));
}
__device__ __forceinline__ void ldsm_x4_trans(unsigned& r0, unsigned& r1,
                                              unsigned& r2, unsigned& r3, uint32_t addr)
{
    asm volatile("ldmatrix.sync.aligned.m8n8.x4.trans.shared.b16 {%0,%1,%2,%3}, [%4];"
                 : "=r"(r0), "=r"(r1), "=r"(r2), "=r"(r3) : "r"(addr));
}
__device__ __forceinline__ void cp16(void* smem, const void* gmem)
{
    const uint32_t s = (uint32_t)__cvta_generic_to_shared(smem);
    asm volatile("cp.async.cg.shared.global [%0], [%1], 16;" :: "r"(s), "l"(gmem));
}

// ---------------------------------------------------------------------------
// K1: projections, 3-way z-split. z=0: p2,p3 (tf32, permuted); z=1: v[0:32];
//     z=2: v[32:64] (bf16, packed stores).
// ---------------------------------------------------------------------------
__global__ void proj_kernel(const float* __restrict__ x,
                            const float* __restrict__ wq2, const float* __restrict__ bq2,
                            const float* __restrict__ wq3, const float* __restrict__ bq3,
                            const float* __restrict__ wv3, const float* __restrict__ bv3)
{
    __shared__ float s_wq2[ND * NCH];
    __shared__ float s_wq3[ND * NCH];
    __shared__ float s_wv[32 * NCH];
    __shared__ float s_b[32];

    const int tid = threadIdx.x;
    const int z   = blockIdx.z;
    const int b   = blockIdx.y;
    const int n   = blockIdx.x * 128 + tid;
    const float* xb = x + (size_t)b * (2 * NCH) * NN;

    if (z == 0) {
        for (int i = tid; i < ND * NCH; i += 128) { s_wq2[i] = wq2[i]; s_wq3[i] = wq3[i]; }
        if (tid < ND)           s_b[tid] = bq2[tid];
        else if (tid < 2 * ND)  s_b[tid] = bq3[tid - ND];
        __syncthreads();

        float p2[ND], p3[ND];
#pragma unroll
        for (int d = 0; d < ND; d++) { p2[d] = s_b[d]; p3[d] = s_b[ND + d]; }
        for (int c = 0; c < NCH; c++) {
            const float x3v = xb[c * NN + n];
            const float x2v = xb[(NCH + c) * NN + n];
#pragma unroll
            for (int d = 0; d < ND; d++) {
                p2[d] = fmaf(s_wq2[d * NCH + c], x2v, p2[d]);
                p3[d] = fmaf(s_wq3[d * NCH + c], x3v, p3[d]);
            }
        }
        float* o2 = g_p2t + ((size_t)b * NN + n) * ND;
        float* o3 = g_p3t + ((size_t)b * NN + n) * ND;
#pragma unroll
        for (int d = 0; d < 4; d++) {            // permuted pair layout
            o2[2 * d]     = to_tf32(p2[d]);
            o2[2 * d + 1] = to_tf32(p2[d + 4]);
            o3[2 * d]     = to_tf32(p3[d]);
            o3[2 * d + 1] = to_tf32(p3[d + 4]);
        }
    } else {
        const int co0 = (z - 1) * 32;
        for (int i = tid; i < 32 * NCH; i += 128) s_wv[i] = wv3[co0 * NCH + i];
        if (tid < 32) s_b[tid] = bv3[co0 + tid];
        __syncthreads();

        float v[32];
#pragma unroll
        for (int c = 0; c < 32; c++) v[c] = s_b[c];
        for (int c = 0; c < NCH; c++) {
            const float x3v = xb[c * NN + n];
#pragma unroll
            for (int o = 0; o < 32; o++)
                v[o] = fmaf(s_wv[o * NCH + c], x3v, v[o]);
        }
        unsigned* ov = (unsigned*)(g_v3b + ((size_t)b * NN + n) * NCH + co0);
#pragma unroll
        for (int c = 0; c < 32; c += 2) ov[c >> 1] = pk_bf16x2(v[c], v[c + 1]);
    }
}

// ---------------------------------------------------------------------------
// K2: single-pass dual attention per (batch, 64-query tile). 256 threads,
//  3 blocks/SM. Warp w: wm=(w&3)*16 (m-block); att=w>>2 (0: att32, 1: att33).
//  Per tile: 8 tf32 score mmas over all 64 keys (keys LDG'd from L2 at tile
//  start) -> ex2 -> register A-frags -> bf16 out-GEMM via ldmatrix.x4.
//  v via cp.async, triple buffered, ONE sync/tile. Atts merged at end.
// ---------------------------------------------------------------------------
__global__ __launch_bounds__(256, 3) void att_kernel(const float* __restrict__ x,
                                                     const float* __restrict__ g2p,
                                                     const float* __restrict__ g3p,
                                                     float* __restrict__ out)
{
    __shared__ __align__(16) __nv_bfloat16 s_v[3][NT * VP];   // 27648B; aliased s_red
    __shared__ __align__(16) float s_z[2][MT];
    __shared__ __align__(16) float s_f32[MT];
    __shared__ __align__(16) float s_f33[MT];

    const int tid  = threadIdx.x;
    const int b    = blockIdx.y;
    const int m0   = blockIdx.x * MT;
    const int warp = tid >> 5;
    const int lane = tid & 31;
    const int g8   = lane >> 2;
    const int l4   = lane & 3;
    const int wm   = (warp & 3) * 16;
    const int att  = warp >> 2;         // 0: att32, 1: att33

    const float* pb2 = g_p2t + (size_t)b * NN * ND;
    const float* pb3 = g_p3t + (size_t)b * NN * ND;
    const float* kb  = att ? pb3 : pb2; // this warp's key projection
    const __nv_bfloat16* vgb = g_v3b + (size_t)b * NN * NCH;

    // q A-fragment (permuted pair layout; pre-scaled by log2 e)
    const float* qb = pb3 + (size_t)m0 * ND;
    const float2 qva = ((const float2*)(qb + (wm + g8) * ND))[l4];
    const float2 qvb = ((const float2*)(qb + (wm + g8 + 8) * ND))[l4];
    const unsigned aq0 = __float_as_uint(qva.x * L2E);
    const unsigned aq1 = __float_as_uint(qvb.x * L2E);
    const unsigned aq2 = __float_as_uint(qva.y * L2E);
    const unsigned aq3 = __float_as_uint(qvb.y * L2E);

    float acc[8][4];                    // 16m x 64c for this warp's att
#pragma unroll
    for (int ct = 0; ct < 8; ct++)
#pragma unroll
        for (int j = 0; j < 4; j++) acc[ct][j] = 0.f;
    float suma = 0.f, sumb = 0.f;       // row sums (rows g8 / g8+8)

    // v staging map: two 16B chunks per thread per tile
    const int fi   = tid * 2;
    const int sof0 = (fi >> 3) * VP + (fi & 7) * 8;             // bf16 units
    const int sof1 = ((fi + 1) >> 3) * VP + ((fi + 1) & 7) * 8;
    const int gof0 = fi * 8;
    const int gof1 = (fi + 1) * 8;

    // preamble: cp.async tiles 0 and 1
    cp16(&s_v[0][sof0], vgb + gof0);
    cp16(&s_v[0][sof1], vgb + gof1);
    asm volatile("cp.async.commit_group;");
    cp16(&s_v[1][sof0], vgb + NT * NCH + gof0);
    cp16(&s_v[1][sof1], vgb + NT * NCH + gof1);
    asm volatile("cp.async.commit_group;");

    for (int t = 0; t < NTILES; t++) {
        const int cur = t % 3;
        if (t == NTILES - 1) asm volatile("cp.async.wait_group 0;");
        else                 asm volatile("cp.async.wait_group 1;");
        __syncthreads();                 // v(t) visible to all
        // issue v(t+2) into buffer (t+2)%3 (not read this iteration)
        if (t + 2 < NTILES) {
            const __nv_bfloat16* src = vgb + (size_t)(t + 2) * NT * NCH;
            __nv_bfloat16* dst = s_v[(t + 2) % 3];
            cp16(dst + sof0, src + gof0);
            cp16(dst + sof1, src + gof1);
            asm volatile("cp.async.commit_group;");
        }

        // keys for this tile (L2-resident; MLP=8 batch of LDG.64)
        float2 kf[8];
#pragma unroll
        for (int i = 0; i < 8; i++)
            kf[i] = ((const float2*)(kb + (t * NT + i * 8 + g8) * ND))[l4];

        // scores over all 64 keys -> ex2 -> register A-fragments
        unsigned afr[4][4];
#pragma unroll
        for (int i = 0; i < 8; i++) {
            float c[4] = {0.f, 0.f, 0.f, 0.f};
            mma_tf32(c, aq0, aq1, aq2, aq3,
                     __float_as_uint(kf[i].x), __float_as_uint(kf[i].y));
            const float e0 = ex2f(c[0]), e1 = ex2f(c[1]);
            const float e2 = ex2f(c[2]), e3 = ex2f(c[3]);
            suma += e0 + e1;
            sumb += e2 + e3;
            afr[i >> 1][(i & 1) * 2 + 0] = pk_bf16x2(e0, e1);
            afr[i >> 1][(i & 1) * 2 + 1] = pk_bf16x2(e2, e3);
        }

        // out GEMM: acc[16m x 64c] += E(16m x 64n) * V(64n x 64c)
#pragma unroll
        for (int kc = 0; kc < 4; kc++) {
            const unsigned a0 = afr[kc][0], a1 = afr[kc][1];
            const unsigned a2 = afr[kc][2], a3 = afr[kc][3];
            const uint32_t rowa = (uint32_t)__cvta_generic_to_shared(
                &s_v[cur][(kc * 16 + (lane & 15)) * VP + ((lane >> 4) << 3)]);
#pragma unroll
            for (int ct = 0; ct < 4; ct++) {
                unsigned b0, b1, b2, b3;
                ldsm_x4_trans(b0, b1, b2, b3, rowa + ct * 32);
                mma_bf16(acc[2 * ct],     a0, a1, a2, a3, b0, b1);
                mma_bf16(acc[2 * ct + 1], a0, a1, a2, a3, b2, b3);
            }
        }
    }

    // ---------------- Z reduction + normalization factors ----------------
    suma += __shfl_xor_sync(0xffffffffu, suma, 1);
    suma += __shfl_xor_sync(0xffffffffu, suma, 2);
    sumb += __shfl_xor_sync(0xffffffffu, sumb, 1);
    sumb += __shfl_xor_sync(0xffffffffu, sumb, 2);
    if (l4 == 0) {
        s_z[att][wm + g8]     = suma;
        s_z[att][wm + g8 + 8] = sumb;
    }
    __syncthreads();
    if (tid < MT) {
        s_f32[tid] = (*g2p) / s_z[0][tid];
        s_f33[tid] = (*g3p) / s_z[1][tid];
    }
    __syncthreads();

    // ---------------- merge atts through smem + epilogue ----------------
    float* s_red = (float*)s_v;          // [64 m][72] fp32 (18432B <= 27648B)
    const float* fs = att ? s_f33 : s_f32;
    const float fa = fs[wm + g8];
    const float fb = fs[wm + g8 + 8];
    if (att == 1) {
#pragma unroll
        for (int ct = 0; ct < 8; ct++) {
            const int c = ct * 8 + 2 * l4;
            *(float2*)&s_red[(wm + g8) * 72 + c]     = make_float2(fa * acc[ct][0], fa * acc[ct][1]);
            *(float2*)&s_red[(wm + g8 + 8) * 72 + c] = make_float2(fb * acc[ct][2], fb * acc[ct][3]);
        }
    }
    __syncthreads();
    if (att == 0) {
#pragma unroll
        for (int ct = 0; ct < 8; ct++) {
            const int c = ct * 8 + 2 * l4;
            float2 lo = *(const float2*)&s_red[(wm + g8) * 72 + c];
            float2 hi = *(const float2*)&s_red[(wm + g8 + 8) * 72 + c];
            lo.x += fa * acc[ct][0]; lo.y += fa * acc[ct][1];
            hi.x += fb * acc[ct][2]; hi.y += fb * acc[ct][3];
            *(float2*)&s_red[(wm + g8) * 72 + c]     = lo;
            *(float2*)&s_red[(wm + g8 + 8) * 72 + c] = hi;
        }
    }
    __syncthreads();
    {
        const float* xb = x + (size_t)b * (2 * NCH) * NN;   // x3 = channels 0..63
        float* ob = out + (size_t)b * NCH * NN;
#pragma unroll
        for (int j = 0; j < 4; j++) {
            const int idx = tid + j * 256;   // 64c x 16 float4-of-m
            const int c   = idx >> 4;
            const int mf  = idx & 15;
            const float4 xv = *(const float4*)(xb + (size_t)c * NN + m0 + mf * 4);
            float4 o;
            o.x = s_red[(mf * 4 + 0) * 72 + c] + xv.x;
            o.y = s_red[(mf * 4 + 1) * 72 + c] + xv.y;
            o.z = s_red[(mf * 4 + 2) * 72 + c] + xv.z;
            o.w = s_red[(mf * 4 + 3) * 72 + c] + xv.w;
            *(float4*)(ob + (size_t)c * NN + m0 + mf * 4) = o;
        }
    }
}

extern "C" void kernel_launch(void* const* d_in, const int* in_sizes, int n_in,
                              void* d_out, int out_size)
{
    const float* x   = (const float*)d_in[0];
    const float* wq2 = (const float*)d_in[1];
    const float* bq2 = (const float*)d_in[2];
    const float* wq3 = (const float*)d_in[3];
    const float* bq3 = (const float*)d_in[4];
    const float* wv3 = (const float*)d_in[5];
    const float* bv3 = (const float*)d_in[6];
    const float* g2  = (const float*)d_in[7];
    const float* g3  = (const float*)d_in[8];
    float* out = (float*)d_out;

    proj_kernel<<<dim3(NN / 128, NB, 3), 128>>>(x, wq2, bq2, wq3, bq3, wv3, bv3);
    att_kernel<<<dim3(NN / MT, NB), 256>>>(x, g2, g3, out);
}

// round 17
// speedup vs baseline: 1.2514x; 1.2514x over previous
#include <cuda_runtime.h>
#include <cuda_bf16.h>
#include <cstdint>

// Problem constants: B=4, C=128, W=H=64
#define NB  4
#define NCH 64
#define ND  8
#define NN  4096
#define MT  64      // query tile -> grid 256
#define NT  64      // key tile
#define NTILES (NN / NT)
#define VP  72      // v-tile pad (bf16 units)
#define L2E 1.4426950408889634f

// Scratch (no cudaMalloc allowed)
// p2t/p3t per token: PERMUTED pairs [d0,d4, d1,d5, d2,d6, d3,d7]
__device__ __align__(16) float         g_p2t[NB * NN * ND];   // tf32-rounded
__device__ __align__(16) float         g_p3t[NB * NN * ND];   // tf32-rounded
__device__ __align__(16) __nv_bfloat16 g_v3b[NB * NN * NCH];  // [b][n][c] bf16

__device__ __forceinline__ float to_tf32(float x) {
    unsigned u;
    asm("cvt.rna.tf32.f32 %0, %1;" : "=r"(u) : "f"(x));
    return __uint_as_float(u);
}
__device__ __forceinline__ float ex2f(float x) {
    float r;
    asm("ex2.approx.f32 %0, %1;" : "=f"(r) : "f"(x));
    return r;
}
__device__ __forceinline__ unsigned pk_bf16x2(float lo, float hi) {
    unsigned r;
    asm("cvt.rn.bf16x2.f32 %0, %1, %2;" : "=r"(r) : "f"(hi), "f"(lo));
    return r;
}
__device__ __forceinline__ void mma_tf32(float* c,
                                         unsigned a0, unsigned a1, unsigned a2, unsigned a3,
                                         unsigned b0, unsigned b1)
{
    asm volatile(
        "mma.sync.aligned.m16n8k8.row.col.f32.tf32.tf32.f32 "
        "{%0,%1,%2,%3}, {%4,%5,%6,%7}, {%8,%9}, {%0,%1,%2,%3};"
        : "+f"(c[0]), "+f"(c[1]), "+f"(c[2]), "+f"(c[3])
        : "r"(a0), "r"(a1), "r"(a2), "r"(a3), "r"(b0), "r"(b1));
}
__device__ __forceinline__ void mma_bf16(float* c,
                                         unsigned a0, unsigned a1, unsigned a2, unsigned a3,
                                         unsigned b0, unsigned b1)
{
    asm volatile(
        "mma.sync.aligned.m16n8k16.row.col.f32.bf16.bf16.f32 "
        "{%0,%1,%2,%3}, {%4,%5,%6,%7}, {%8,%9}, {%0,%1,%2,%3};"
        : "+f"(c[0]), "+f"(c[1]), "+f"(c[2]), "+f"(c[3])
        : "r"(a0), "r"(a1), "r"(a2), "r"(a3), "r"(b0), "r"(b1));
}
__device__ __forceinline__ void ldsm_x4_trans(unsigned& r0, unsigned& r1,
                                              unsigned& r2, unsigned& r3, uint32_t addr)
{
    asm volatile("ldmatrix.sync.aligned.m8n8.x4.trans.shared.b16 {%0,%1,%2,%3}, [%4];"
                 : "=r"(r0), "=r"(r1), "=r"(r2), "=r"(r3) : "r"(addr));
}
__device__ __forceinline__ void cp16(void* smem, const void* gmem)
{
    const uint32_t s = (uint32_t)__cvta_generic_to_shared(smem);
    asm volatile("cp.async.cg.shared.global [%0], [%1], 16;" :: "r"(s), "l"(gmem));
}

// ---------------------------------------------------------------------------
// K1: projections, 3-way z-split. z=0: p2,p3 (tf32, permuted); z=1: v[0:32];
//     z=2: v[32:64] (bf16, packed stores).
// ---------------------------------------------------------------------------
__global__ void proj_kernel(const float* __restrict__ x,
                            const float* __restrict__ wq2, const float* __restrict__ bq2,
                            const float* __restrict__ wq3, const float* __restrict__ bq3,
                            const float* __restrict__ wv3, const float* __restrict__ bv3)
{
    __shared__ float s_wq2[ND * NCH];
    __shared__ float s_wq3[ND * NCH];
    __shared__ float s_wv[32 * NCH];
    __shared__ float s_b[32];

    const int tid = threadIdx.x;
    const int z   = blockIdx.z;
    const int b   = blockIdx.y;
    const int n   = blockIdx.x * 128 + tid;
    const float* xb = x + (size_t)b * (2 * NCH) * NN;

    if (z == 0) {
        for (int i = tid; i < ND * NCH; i += 128) { s_wq2[i] = wq2[i]; s_wq3[i] = wq3[i]; }
        if (tid < ND)           s_b[tid] = bq2[tid];
        else if (tid < 2 * ND)  s_b[tid] = bq3[tid - ND];
        __syncthreads();

        float p2[ND], p3[ND];
#pragma unroll
        for (int d = 0; d < ND; d++) { p2[d] = s_b[d]; p3[d] = s_b[ND + d]; }
        for (int c = 0; c < NCH; c++) {
            const float x3v = xb[c * NN + n];
            const float x2v = xb[(NCH + c) * NN + n];
#pragma unroll
            for (int d = 0; d < ND; d++) {
                p2[d] = fmaf(s_wq2[d * NCH + c], x2v, p2[d]);
                p3[d] = fmaf(s_wq3[d * NCH + c], x3v, p3[d]);
            }
        }
        float* o2 = g_p2t + ((size_t)b * NN + n) * ND;
        float* o3 = g_p3t + ((size_t)b * NN + n) * ND;
#pragma unroll
        for (int d = 0; d < 4; d++) {            // permuted pair layout
            o2[2 * d]     = to_tf32(p2[d]);
            o2[2 * d + 1] = to_tf32(p2[d + 4]);
            o3[2 * d]     = to_tf32(p3[d]);
            o3[2 * d + 1] = to_tf32(p3[d + 4]);
        }
    } else {
        const int co0 = (z - 1) * 32;
        for (int i = tid; i < 32 * NCH; i += 128) s_wv[i] = wv3[co0 * NCH + i];
        if (tid < 32) s_b[tid] = bv3[co0 + tid];
        __syncthreads();

        float v[32];
#pragma unroll
        for (int c = 0; c < 32; c++) v[c] = s_b[c];
        for (int c = 0; c < NCH; c++) {
            const float x3v = xb[c * NN + n];
#pragma unroll
            for (int o = 0; o < 32; o++)
                v[o] = fmaf(s_wv[o * NCH + c], x3v, v[o]);
        }
        unsigned* ov = (unsigned*)(g_v3b + ((size_t)b * NN + n) * NCH + co0);
#pragma unroll
        for (int c = 0; c < 32; c += 2) ov[c >> 1] = pk_bf16x2(v[c], v[c + 1]);
    }
}

// ---------------------------------------------------------------------------
// K2: single-pass dual attention per (batch, 64-query tile). 256 threads.
//  Warp w: wm=(w&3)*16 (m-block); att=w>>2 (0: att32/p2-keys, 1: att33/p3).
//  Per tile: 8 tf32 score mmas (keys prefetched cross-tile) -> ex2 ->
//  register A-frags -> bf16 out-GEMM with BATCHED ldmatrix.x4.
//  v via cp.async, triple buffered, ONE sync/tile. Atts merged at end.
// ---------------------------------------------------------------------------
__global__ __launch_bounds__(256, 2) void att_kernel(const float* __restrict__ x,
                                                     const float* __restrict__ g2p,
                                                     const float* __restrict__ g3p,
                                                     float* __restrict__ out)
{
    __shared__ __align__(16) __nv_bfloat16 s_v[3][NT * VP];   // 27648B; aliased s_red
    __shared__ __align__(16) float s_z[2][MT];
    __shared__ __align__(16) float s_f32[MT];
    __shared__ __align__(16) float s_f33[MT];

    const int tid  = threadIdx.x;
    const int b    = blockIdx.y;
    const int m0   = blockIdx.x * MT;
    const int warp = tid >> 5;
    const int lane = tid & 31;
    const int g8   = lane >> 2;
    const int l4   = lane & 3;
    const int wm   = (warp & 3) * 16;
    const int att  = warp >> 2;         // 0: att32, 1: att33

    const float* pb2 = g_p2t + (size_t)b * NN * ND;
    const float* pb3 = g_p3t + (size_t)b * NN * ND;
    const float* kb  = att ? pb3 : pb2; // this warp's key projection
    const __nv_bfloat16* vgb = g_v3b + (size_t)b * NN * NCH;

    // q A-fragment (permuted pair layout; pre-scaled by log2 e)
    const float* qb = pb3 + (size_t)m0 * ND;
    const float2 qva = ((const float2*)(qb + (wm + g8) * ND))[l4];
    const float2 qvb = ((const float2*)(qb + (wm + g8 + 8) * ND))[l4];
    const unsigned aq0 = __float_as_uint(qva.x * L2E);
    const unsigned aq1 = __float_as_uint(qvb.x * L2E);
    const unsigned aq2 = __float_as_uint(qva.y * L2E);
    const unsigned aq3 = __float_as_uint(qvb.y * L2E);

    float acc[8][4];                    // 16m x 64c for this warp's att
#pragma unroll
    for (int ct = 0; ct < 8; ct++)
#pragma unroll
        for (int j = 0; j < 4; j++) acc[ct][j] = 0.f;
    float suma = 0.f, sumb = 0.f;       // row sums (rows g8 / g8+8)

    // v staging map: two 16B chunks per thread per tile
    const int fi   = tid * 2;
    const int sof0 = (fi >> 3) * VP + (fi & 7) * 8;             // bf16 units
    const int sof1 = ((fi + 1) >> 3) * VP + ((fi + 1) & 7) * 8;
    const int gof0 = fi * 8;
    const int gof1 = (fi + 1) * 8;

    // preamble: cp.async tiles 0,1; prefetch keys(0) into registers
    cp16(&s_v[0][sof0], vgb + gof0);
    cp16(&s_v[0][sof1], vgb + gof1);
    asm volatile("cp.async.commit_group;");
    cp16(&s_v[1][sof0], vgb + NT * NCH + gof0);
    cp16(&s_v[1][sof1], vgb + NT * NCH + gof1);
    asm volatile("cp.async.commit_group;");
    float2 kf[8];
#pragma unroll
    for (int i = 0; i < 8; i++)
        kf[i] = ((const float2*)(kb + (i * 8 + g8) * ND))[l4];

    for (int t = 0; t < NTILES; t++) {
        const int cur = t % 3;
        if (t == NTILES - 1) asm volatile("cp.async.wait_group 0;");
        else                 asm volatile("cp.async.wait_group 1;");
        __syncthreads();                 // v(t) visible to all
        // issue v(t+2) into buffer (t+2)%3 (not read this iteration)
        if (t + 2 < NTILES) {
            const __nv_bfloat16* src = vgb + (size_t)(t + 2) * NT * NCH;
            __nv_bfloat16* dst = s_v[(t + 2) % 3];
            cp16(dst + sof0, src + gof0);
            cp16(dst + sof1, src + gof1);
            asm volatile("cp.async.commit_group;");
        }

        // scores over all 64 keys -> ex2 -> register A-fragments
        unsigned afr[4][4];
#pragma unroll
        for (int i = 0; i < 8; i++) {
            float c[4] = {0.f, 0.f, 0.f, 0.f};
            mma_tf32(c, aq0, aq1, aq2, aq3,
                     __float_as_uint(kf[i].x), __float_as_uint(kf[i].y));
            const float e0 = ex2f(c[0]), e1 = ex2f(c[1]);
            const float e2 = ex2f(c[2]), e3 = ex2f(c[3]);
            suma += e0 + e1;
            sumb += e2 + e3;
            afr[i >> 1][(i & 1) * 2 + 0] = pk_bf16x2(e0, e1);
            afr[i >> 1][(i & 1) * 2 + 1] = pk_bf16x2(e2, e3);
        }
        // prefetch keys(t+1) — lands during the GEMM below
        if (t + 1 < NTILES) {
#pragma unroll
            for (int i = 0; i < 8; i++)
                kf[i] = ((const float2*)(kb + ((t + 1) * NT + i * 8 + g8) * ND))[l4];
        }

        // out GEMM: acc[16m x 64c] += E(16m x 64n) * V(64n x 64c)
        // batched ldsm (MLP=4) then mma
#pragma unroll
        for (int kc = 0; kc < 4; kc++) {
            const unsigned a0 = afr[kc][0], a1 = afr[kc][1];
            const unsigned a2 = afr[kc][2], a3 = afr[kc][3];
            const uint32_t rowa = (uint32_t)__cvta_generic_to_shared(
                &s_v[cur][(kc * 16 + (lane & 15)) * VP + ((lane >> 4) << 3)]);
            unsigned bf[16];
#pragma unroll
            for (int ct = 0; ct < 4; ct++)
                ldsm_x4_trans(bf[4 * ct], bf[4 * ct + 1], bf[4 * ct + 2], bf[4 * ct + 3],
                              rowa + ct * 32);
#pragma unroll
            for (int ct = 0; ct < 4; ct++) {
                mma_bf16(acc[2 * ct],     a0, a1, a2, a3, bf[4 * ct],     bf[4 * ct + 1]);
                mma_bf16(acc[2 * ct + 1], a0, a1, a2, a3, bf[4 * ct + 2], bf[4 * ct + 3]);
            }
        }
    }

    // ---------------- Z reduction + normalization factors ----------------
    suma += __shfl_xor_sync(0xffffffffu, suma, 1);
    suma += __shfl_xor_sync(0xffffffffu, suma, 2);
    sumb += __shfl_xor_sync(0xffffffffu, sumb, 1);
    sumb += __shfl_xor_sync(0xffffffffu, sumb, 2);
    if (l4 == 0) {
        s_z[att][wm + g8]     = suma;
        s_z[att][wm + g8 + 8] = sumb;
    }
    __syncthreads();
    if (tid < MT) {
        s_f32[tid] = (*g2p) / s_z[0][tid];
        s_f33[tid] = (*g3p) / s_z[1][tid];
    }
    __syncthreads();

    // ---------------- merge atts through smem + epilogue ----------------
    float* s_red = (float*)s_v;          // [64 m][72] fp32 (18432B <= 27648B)
    const float* fs = att ? s_f33 : s_f32;
    const float fa = fs[wm + g8];
    const float fb = fs[wm + g8 + 8];
    if (att == 1) {
#pragma unroll
        for (int ct = 0; ct < 8; ct++) {
            const int c = ct * 8 + 2 * l4;
            *(float2*)&s_red[(wm + g8) * 72 + c]     = make_float2(fa * acc[ct][0], fa * acc[ct][1]);
            *(float2*)&s_red[(wm + g8 + 8) * 72 + c] = make_float2(fb * acc[ct][2], fb * acc[ct][3]);
        }
    }
    __syncthreads();
    if (att == 0) {
#pragma unroll
        for (int ct = 0; ct < 8; ct++) {
            const int c = ct * 8 + 2 * l4;
            float2 lo = *(const float2*)&s_red[(wm + g8) * 72 + c];
            float2 hi = *(const float2*)&s_red[(wm + g8 + 8) * 72 + c];
            lo.x += fa * acc[ct][0]; lo.y += fa * acc[ct][1];
            hi.x += fb * acc[ct][2]; hi.y += fb * acc[ct][3];
            *(float2*)&s_red[(wm + g8) * 72 + c]     = lo;
            *(float2*)&s_red[(wm + g8 + 8) * 72 + c] = hi;
        }
    }
    __syncthreads();
    {
        const float* xb = x + (size_t)b * (2 * NCH) * NN;   // x3 = channels 0..63
        float* ob = out + (size_t)b * NCH * NN;
#pragma unroll
        for (int j = 0; j < 4; j++) {
            const int idx = tid + j * 256;   // 64c x 16 float4-of-m
            const int c   = idx >> 4;
            const int mf  = idx & 15;
            const float4 xv = *(const float4*)(xb + (size_t)c * NN + m0 + mf * 4);
            float4 o;
            o.x = s_red[(mf * 4 + 0) * 72 + c] + xv.x;
            o.y = s_red[(mf * 4 + 1) * 72 + c] + xv.y;
            o.z = s_red[(mf * 4 + 2) * 72 + c] + xv.z;
            o.w = s_red[(mf * 4 + 3) * 72 + c] + xv.w;
            *(float4*)(ob + (size_t)c * NN + m0 + mf * 4) = o;
        }
    }
}

extern "C" void kernel_launch(void* const* d_in, const int* in_sizes, int n_in,
                              void* d_out, int out_size)
{
    const float* x   = (const float*)d_in[0];
    const float* wq2 = (const float*)d_in[1];
    const float* bq2 = (const float*)d_in[2];
    const float* wq3 = (const float*)d_in[3];
    const float* bq3 = (const float*)d_in[4];
    const float* wv3 = (const float*)d_in[5];
    const float* bv3 = (const float*)d_in[6];
    const float* g2  = (const float*)d_in[7];
    const float* g3  = (const float*)d_in[8];
    float* out = (float*)d_out;

    proj_kernel<<<dim3(NN / 128, NB, 3), 128>>>(x, wq2, bq2, wq3, bq3, wv3, bv3);
    att_kernel<<<dim3(NN / MT, NB), 256>>>(x, g2, g3, out);
}